// round 6
// baseline (speedup 1.0000x reference)
#include <cuda_runtime.h>
#include <math.h>
#include <stdint.h>

#define NN 50000
#define EE 800000
#define HD 256
#define NH 4
#define DH 64

// ---- static scratch (no allocations allowed) ----
__device__ float g_q[(size_t)NN * HD];
__device__ float g_k[(size_t)NN * HD];
__device__ float g_v[(size_t)NN * HD];
__device__ float g_skip[(size_t)NN * HD];
__device__ int   g_deg[NN];
__device__ int   g_rowptr[NN + 1];
__device__ int   g_cursor[NN];
__device__ int   g_cidx[EE];

// ---------------------------------------------------------------------------
// CSR build: zero degree -> histogram -> scan -> scatter
// ---------------------------------------------------------------------------
__global__ void zero_deg(int n) {
    int i = blockIdx.x * blockDim.x + threadIdx.x;
    if (i < n) g_deg[i] = 0;
}

__global__ void hist_kernel(const int* __restrict__ dst, int E) {
    int i = blockIdx.x * blockDim.x + threadIdx.x;
    if (i < E) atomicAdd(&g_deg[dst[i]], 1);
}

__global__ __launch_bounds__(1024) void scan_kernel(int n) {
    const int T = 1024;
    const int per = (NN + T - 1) / T;
    __shared__ int sm[T];
    int t = threadIdx.x;
    int base = t * per;
    int s = 0;
    for (int i = 0; i < per; i++) {
        int idx = base + i;
        if (idx < n) s += g_deg[idx];
    }
    sm[t] = s;
    __syncthreads();
    for (int off = 1; off < T; off <<= 1) {
        int v = (t >= off) ? sm[t - off] : 0;
        __syncthreads();
        sm[t] += v;
        __syncthreads();
    }
    int run = sm[t] - s;
    for (int i = 0; i < per; i++) {
        int idx = base + i;
        if (idx < n) {
            g_rowptr[idx] = run;
            g_cursor[idx] = run;
            run += g_deg[idx];
        }
    }
    if (t == T - 1) g_rowptr[n] = run;
}

__global__ void scatter_kernel(const int* __restrict__ src,
                               const int* __restrict__ dst, int E) {
    int i = blockIdx.x * blockDim.x + threadIdx.x;
    if (i < E) {
        int pos = atomicAdd(&g_cursor[dst[i]], 1);
        g_cidx[pos] = src[i];
    }
}

// ---------------------------------------------------------------------------
// tf32 / cp.async helpers
// ---------------------------------------------------------------------------
__device__ __forceinline__ uint32_t f2tf32(float x) {
    uint32_t r;
    asm("cvt.rna.tf32.f32 %0, %1;" : "=r"(r) : "f"(x));
    return r;
}

__device__ __forceinline__ void mma_tf32(float c[4],
    uint32_t a0, uint32_t a1, uint32_t a2, uint32_t a3,
    uint32_t b0, uint32_t b1)
{
    asm volatile(
        "mma.sync.aligned.m16n8k8.row.col.f32.tf32.tf32.f32 "
        "{%0,%1,%2,%3}, {%4,%5,%6,%7}, {%8,%9}, {%0,%1,%2,%3};\n"
        : "+f"(c[0]), "+f"(c[1]), "+f"(c[2]), "+f"(c[3])
        : "r"(a0), "r"(a1), "r"(a2), "r"(a3), "r"(b0), "r"(b1));
}

__device__ __forceinline__ void cp16(uint32_t saddr, const void* g, bool pred) {
    int sz = pred ? 16 : 0;
    asm volatile("cp.async.cg.shared.global [%0], [%1], 16, %2;"
        :: "r"(saddr), "l"(g), "r"(sz));
}
__device__ __forceinline__ void cp_commit() {
    asm volatile("cp.async.commit_group;");
}
template <int N>
__device__ __forceinline__ void cp_wait() {
    asm volatile("cp.async.wait_group %0;" :: "n"(N));
}

// ---------------------------------------------------------------------------
// 4 projections, tf32 tensor-core GEMM (NT): C = feat @ W^T + b
// BM=128, BN=64, BK=16, 256 threads (8 warps 4x2), warp tile 32x32.
// 3-stage cp.async pipeline; smem row-major fp32, stride 16 (unpadded).
// Fragment loads are LDS.128 over a k-permutation shared by A and B:
// thread (gid,tig) owns physical k {4tig..4tig+3}; mma0 uses .xy, mma1 .zw.
// addr mod 32 = 16*gid + 4*tig => conflict-free per 8-lane phase.
// ---------------------------------------------------------------------------
#define GBM 128
#define GBN 64
#define GBK 16
#define NKT 16       // 256 / GBK

__global__ __launch_bounds__(256) void proj_gemm_tf32(
    const float* __restrict__ feat,
    const float* __restrict__ Wq, const float* __restrict__ bq,
    const float* __restrict__ Wk, const float* __restrict__ bk,
    const float* __restrict__ Wv, const float* __restrict__ bv,
    const float* __restrict__ Ws, const float* __restrict__ bs,
    int M)
{
    __shared__ float As[3][GBM][GBK];
    __shared__ float Bs[3][GBN][GBK];

    const float* W;
    const float* bias;
    float* C;
    switch (blockIdx.z) {
        case 0:  W = Wq; bias = bq; C = g_q;    break;
        case 1:  W = Wk; bias = bk; C = g_k;    break;
        case 2:  W = Wv; bias = bv; C = g_v;    break;
        default: W = Ws; bias = bs; C = g_skip; break;
    }

    const int tid   = threadIdx.x;
    const int lane  = tid & 31;
    const int warp  = tid >> 5;
    const int warpM = warp & 3;
    const int warpN = warp >> 2;
    const int bm = blockIdx.y * GBM;
    const int bn = blockIdx.x * GBN;

    const int gid = lane >> 2;
    const int tig = lane & 3;

    // copy assignments
    const int ar0 = tid >> 2;             // A rows: ar0 and ar0+64
    const int akc = (tid & 3) * 4;        // k chunk within tile
    const int br0 = tid >> 2;             // B row 0..63

    uint32_t sA = (uint32_t)__cvta_generic_to_shared(&As[0][0][0]);
    uint32_t sB = (uint32_t)__cvta_generic_to_shared(&Bs[0][0][0]);
    const uint32_t stageA = GBM * GBK * 4;
    const uint32_t stageB = GBN * GBK * 4;

    float acc[2][4][4] = {};

    auto load_stage = [&](int j, int st) {
        int kk = j * GBK;
        {
            int row = ar0;
            int grow = bm + row;
            cp16(sA + st * stageA + (row * GBK + akc) * 4,
                 feat + (size_t)grow * 256 + kk + akc, grow < M);
            row = ar0 + 64;
            grow = bm + row;
            cp16(sA + st * stageA + (row * GBK + akc) * 4,
                 feat + (size_t)grow * 256 + kk + akc, grow < M);
        }
        cp16(sB + st * stageB + (br0 * GBK + akc) * 4,
             W + (size_t)(bn + br0) * 256 + kk + akc, true);
        cp_commit();
    };

    load_stage(0, 0);
    load_stage(1, 1);

    for (int i = 0; i < NKT; i++) {
        if (i + 1 < NKT) cp_wait<1>(); else cp_wait<0>();
        __syncthreads();

        int st = i % 3;
        const float4* As4 = (const float4*)&As[st][0][0]; // [row*4 + tig]
        const float4* Bs4 = (const float4*)&Bs[st][0][0];

        // wide fragment loads (LDS.128, conflict-free)
        float4 a4[2][2];
        #pragma unroll
        for (int mt = 0; mt < 2; mt++) {
            int r = warpM * 32 + mt * 16 + gid;
            a4[mt][0] = As4[r * 4 + tig];
            a4[mt][1] = As4[(r + 8) * 4 + tig];
        }
        float4 b4[4];
        #pragma unroll
        for (int nt = 0; nt < 4; nt++) {
            int nidx = warpN * 32 + nt * 8 + gid;
            b4[nt] = Bs4[nidx * 4 + tig];
        }

        // convert to tf32
        uint32_t aa[2][2][4];
        #pragma unroll
        for (int mt = 0; mt < 2; mt++)
            #pragma unroll
            for (int rr = 0; rr < 2; rr++) {
                aa[mt][rr][0] = f2tf32(a4[mt][rr].x);
                aa[mt][rr][1] = f2tf32(a4[mt][rr].y);
                aa[mt][rr][2] = f2tf32(a4[mt][rr].z);
                aa[mt][rr][3] = f2tf32(a4[mt][rr].w);
            }
        uint32_t bb[4][4];
        #pragma unroll
        for (int nt = 0; nt < 4; nt++) {
            bb[nt][0] = f2tf32(b4[nt].x);
            bb[nt][1] = f2tf32(b4[nt].y);
            bb[nt][2] = f2tf32(b4[nt].z);
            bb[nt][3] = f2tf32(b4[nt].w);
        }

        // two 8-k mmas per tile pair: halves .xy and .zw
        #pragma unroll
        for (int mt = 0; mt < 2; mt++)
            #pragma unroll
            for (int nt = 0; nt < 4; nt++) {
                mma_tf32(acc[mt][nt],
                         aa[mt][0][0], aa[mt][1][0], aa[mt][0][1], aa[mt][1][1],
                         bb[nt][0], bb[nt][1]);
                mma_tf32(acc[mt][nt],
                         aa[mt][0][2], aa[mt][1][2], aa[mt][0][3], aa[mt][1][3],
                         bb[nt][2], bb[nt][3]);
            }

        if (i + 2 < NKT) load_stage(i + 2, (i + 2) % 3);
    }

    #pragma unroll
    for (int mt = 0; mt < 2; mt++) {
        int row = bm + warpM * 32 + mt * 16 + gid;
        #pragma unroll
        for (int nt = 0; nt < 4; nt++) {
            int col = bn + warpN * 32 + nt * 8 + tig * 2;
            float b0 = bias[col], b1 = bias[col + 1];
            if (row < M) {
                float2 o = make_float2(acc[mt][nt][0] + b0, acc[mt][nt][1] + b1);
                *(float2*)(C + (size_t)row * 256 + col) = o;
            }
            if (row + 8 < M) {
                float2 o = make_float2(acc[mt][nt][2] + b0, acc[mt][nt][3] + b1);
                *(float2*)(C + (size_t)(row + 8) * 256 + col) = o;
            }
        }
    }
}

// ---------------------------------------------------------------------------
// fused dst-centric attention + gated skip + LN + PReLU.  one warp per node.
// Scores are tiny (|e| < ~0.6): exp without max-subtraction is exact-equivalent.
// ---------------------------------------------------------------------------
__global__ __launch_bounds__(256) void fused_node(
    const float* __restrict__ Wg, const float* __restrict__ bg,
    const float* __restrict__ lnw, const float* __restrict__ lnb,
    const float* __restrict__ prelu_a, float* __restrict__ out, int N)
{
    int w    = (int)((blockIdx.x * 256u + threadIdx.x) >> 5);
    int lane = threadIdx.x & 31;
    if (w >= N) return;

    const float4* kr = (const float4*)(g_k + (size_t)w * HD);
    float4 k0 = kr[lane * 2], k1 = kr[lane * 2 + 1];

    float acc[8] = {};
    float den = 0.0f;

    int beg = g_rowptr[w];
    int end = g_rowptr[w + 1];
    for (int j = beg; j < end; j++) {
        int s = g_cidx[j];
        const float4* qr = (const float4*)(g_q + (size_t)s * HD);
        float4 q0 = qr[lane * 2], q1 = qr[lane * 2 + 1];
        const float4* vr = (const float4*)(g_v + (size_t)s * HD);
        float4 v0 = vr[lane * 2], v1 = vr[lane * 2 + 1];

        float p = q0.x * k0.x + q0.y * k0.y + q0.z * k0.z + q0.w * k0.w
                + q1.x * k1.x + q1.y * k1.y + q1.z * k1.z + q1.w * k1.w;
        p += __shfl_xor_sync(0xffffffffu, p, 4);
        p += __shfl_xor_sync(0xffffffffu, p, 2);
        p += __shfl_xor_sync(0xffffffffu, p, 1);
        float ex = __expf(p * 0.125f);
        den += ex;

        acc[0] += ex * v0.x; acc[1] += ex * v0.y;
        acc[2] += ex * v0.z; acc[3] += ex * v0.w;
        acc[4] += ex * v1.x; acc[5] += ex * v1.y;
        acc[6] += ex * v1.z; acc[7] += ex * v1.w;
    }

    float inv = (den > 0.0f) ? (1.0f / den) : 0.0f;
    float rs[8];
    #pragma unroll
    for (int i = 0; i < 8; i++) rs[i] = acc[i] * inv;

    const float4* skp = (const float4*)(g_skip + (size_t)w * HD);
    float4 s0 = skp[lane * 2], s1 = skp[lane * 2 + 1];
    float sk[8] = {s0.x, s0.y, s0.z, s0.w, s1.x, s1.y, s1.z, s1.w};

    float gp = 0.0f;
    #pragma unroll
    for (int i = 0; i < 8; i++) {
        int c = lane * 8 + i;
        gp += sk[i] * Wg[c] + rs[i] * Wg[256 + c] + (sk[i] - rs[i]) * Wg[512 + c];
    }
    #pragma unroll
    for (int m = 16; m >= 1; m >>= 1) gp += __shfl_xor_sync(0xffffffffu, gp, m);
    float g = 1.0f / (1.0f + expf(-(gp + bg[0])));

    float x[8];
    float sum = 0.0f;
    #pragma unroll
    for (int i = 0; i < 8; i++) {
        x[i] = g * sk[i] + (1.0f - g) * rs[i];
        sum += x[i];
    }
    #pragma unroll
    for (int m = 16; m >= 1; m >>= 1) sum += __shfl_xor_sync(0xffffffffu, sum, m);
    float mu = sum * (1.0f / 256.0f);

    float vs = 0.0f;
    #pragma unroll
    for (int i = 0; i < 8; i++) {
        float dd = x[i] - mu;
        vs += dd * dd;
    }
    #pragma unroll
    for (int m = 16; m >= 1; m >>= 1) vs += __shfl_xor_sync(0xffffffffu, vs, m);
    float rstd = rsqrtf(vs * (1.0f / 256.0f) + 1e-5f);

    float a = *prelu_a;
    float o[8];
    #pragma unroll
    for (int i = 0; i < 8; i++) {
        int c = lane * 8 + i;
        float y = (x[i] - mu) * rstd * lnw[c] + lnb[c];
        o[i] = (y >= 0.0f) ? y : a * y;
    }
    float4* op = (float4*)(out + (size_t)w * HD);
    op[lane * 2]     = make_float4(o[0], o[1], o[2], o[3]);
    op[lane * 2 + 1] = make_float4(o[4], o[5], o[6], o[7]);
}

// ---------------------------------------------------------------------------
extern "C" void kernel_launch(void* const* d_in, const int* in_sizes, int n_in,
                              void* d_out, int out_size)
{
    const float* feat = (const float*)d_in[0];
    const int*   src  = (const int*)d_in[1];
    const int*   dst  = (const int*)d_in[2];
    const float* Wq = (const float*)d_in[3];  const float* bq = (const float*)d_in[4];
    const float* Wk = (const float*)d_in[5];  const float* bk = (const float*)d_in[6];
    const float* Wv = (const float*)d_in[7];  const float* bv = (const float*)d_in[8];
    const float* Ws = (const float*)d_in[9];  const float* bs = (const float*)d_in[10];
    const float* Wg = (const float*)d_in[11]; const float* bg = (const float*)d_in[12];
    const float* lnw = (const float*)d_in[13];
    const float* lnb = (const float*)d_in[14];
    const float* pa  = (const float*)d_in[15];
    float* out = (float*)d_out;

    int M = in_sizes[0] / HD;   // 50000
    int E = in_sizes[1];        // 800000
    if (M > NN) M = NN;
    if (E > EE) E = EE;

    // CSR build
    zero_deg<<<(M + 255) / 256, 256>>>(M);
    hist_kernel<<<(E + 255) / 256, 256>>>(dst, E);
    scan_kernel<<<1, 1024>>>(M);
    scatter_kernel<<<(E + 255) / 256, 256>>>(src, dst, E);

    // projections
    dim3 gg(HD / GBN, (M + GBM - 1) / GBM, 4);
    proj_gemm_tf32<<<gg, 256>>>(feat, Wq, bq, Wk, bk, Wv, bv, Ws, bs, M);

    // fused attention + epilogue (one warp per node)
    fused_node<<<(M + 7) / 8, 256>>>(Wg, bg, lnw, lnb, pa, out, M);
}

// round 7
// speedup vs baseline: 1.1165x; 1.1165x over previous
#include <cuda_runtime.h>
#include <math.h>
#include <stdint.h>

#define NN 50000
#define EE 800000
#define HD 256
#define NH 4
#define DH 64

// ---- static scratch (no allocations allowed) ----
__device__ float g_q[(size_t)NN * HD];
__device__ float g_k[(size_t)NN * HD];
__device__ float g_v[(size_t)NN * HD];
__device__ float g_skip[(size_t)NN * HD];
__device__ float g_featr[(size_t)NN * HD];     // feat pre-rounded to tf32 bits
__device__ float g_wr[4][HD * HD];             // Wq/Wk/Wv/Wskip pre-rounded
__device__ int   g_deg[NN];
__device__ int   g_rowptr[NN + 1];
__device__ int   g_cursor[NN];
__device__ int   g_cidx[EE];

// ---------------------------------------------------------------------------
// CSR build: zero degree -> histogram -> scan -> scatter
// ---------------------------------------------------------------------------
__global__ void zero_deg(int n) {
    int i = blockIdx.x * blockDim.x + threadIdx.x;
    if (i < n) g_deg[i] = 0;
}

__global__ void hist_kernel(const int* __restrict__ dst, int E) {
    int i = blockIdx.x * blockDim.x + threadIdx.x;
    if (i < E) atomicAdd(&g_deg[dst[i]], 1);
}

__global__ __launch_bounds__(1024) void scan_kernel(int n) {
    const int T = 1024;
    const int per = (NN + T - 1) / T;
    __shared__ int sm[T];
    int t = threadIdx.x;
    int base = t * per;
    int s = 0;
    for (int i = 0; i < per; i++) {
        int idx = base + i;
        if (idx < n) s += g_deg[idx];
    }
    sm[t] = s;
    __syncthreads();
    for (int off = 1; off < T; off <<= 1) {
        int v = (t >= off) ? sm[t - off] : 0;
        __syncthreads();
        sm[t] += v;
        __syncthreads();
    }
    int run = sm[t] - s;
    for (int i = 0; i < per; i++) {
        int idx = base + i;
        if (idx < n) {
            g_rowptr[idx] = run;
            g_cursor[idx] = run;
            run += g_deg[idx];
        }
    }
    if (t == T - 1) g_rowptr[n] = run;
}

__global__ void scatter_kernel(const int* __restrict__ src,
                               const int* __restrict__ dst, int E) {
    int i = blockIdx.x * blockDim.x + threadIdx.x;
    if (i < E) {
        int pos = atomicAdd(&g_cursor[dst[i]], 1);
        g_cidx[pos] = src[i];
    }
}

// ---------------------------------------------------------------------------
// tf32 / cp.async helpers
// ---------------------------------------------------------------------------
__device__ __forceinline__ uint32_t f2tf32(float x) {
    uint32_t r;
    asm("cvt.rna.tf32.f32 %0, %1;" : "=r"(r) : "f"(x));
    return r;
}

__device__ __forceinline__ void mma_tf32(float c[4],
    uint32_t a0, uint32_t a1, uint32_t a2, uint32_t a3,
    uint32_t b0, uint32_t b1)
{
    asm volatile(
        "mma.sync.aligned.m16n8k8.row.col.f32.tf32.tf32.f32 "
        "{%0,%1,%2,%3}, {%4,%5,%6,%7}, {%8,%9}, {%0,%1,%2,%3};\n"
        : "+f"(c[0]), "+f"(c[1]), "+f"(c[2]), "+f"(c[3])
        : "r"(a0), "r"(a1), "r"(a2), "r"(a3), "r"(b0), "r"(b1));
}

__device__ __forceinline__ void cp16(uint32_t saddr, const void* g, bool pred) {
    int sz = pred ? 16 : 0;
    asm volatile("cp.async.cg.shared.global [%0], [%1], 16, %2;"
        :: "r"(saddr), "l"(g), "r"(sz));
}
__device__ __forceinline__ void cp_commit() {
    asm volatile("cp.async.commit_group;");
}
template <int N>
__device__ __forceinline__ void cp_wait() {
    asm volatile("cp.async.wait_group %0;" :: "n"(N));
}

// ---------------------------------------------------------------------------
// pre-round feat / W to tf32 bit patterns (idempotent through memory)
// ---------------------------------------------------------------------------
__global__ void round_feat(const float* __restrict__ feat, int n4) {
    int i = blockIdx.x * blockDim.x + threadIdx.x;
    if (i >= n4) return;
    float4 x = ((const float4*)feat)[i];
    float4 o;
    o.x = __uint_as_float(f2tf32(x.x));
    o.y = __uint_as_float(f2tf32(x.y));
    o.z = __uint_as_float(f2tf32(x.z));
    o.w = __uint_as_float(f2tf32(x.w));
    ((float4*)g_featr)[i] = o;
}

__global__ void round_w(const float* __restrict__ Wq, const float* __restrict__ Wk,
                        const float* __restrict__ Wv, const float* __restrict__ Ws) {
    int i = blockIdx.x * blockDim.x + threadIdx.x;   // 0 .. HD*HD/4-1
    const float* src[4] = {Wq, Wk, Wv, Ws};
    #pragma unroll
    for (int z = 0; z < 4; z++) {
        float4 x = ((const float4*)src[z])[i];
        float4 o;
        o.x = __uint_as_float(f2tf32(x.x));
        o.y = __uint_as_float(f2tf32(x.y));
        o.z = __uint_as_float(f2tf32(x.z));
        o.w = __uint_as_float(f2tf32(x.w));
        ((float4*)g_wr[z])[i] = o;
    }
}

// ---------------------------------------------------------------------------
// 4 projections, tf32 tensor-core GEMM (NT): C = featr @ Wr^T + b
// BM=128, BN=64, BK=16, 256 threads (8 warps 4x2), warp tile 32x32.
// 3-stage cp.async pipeline; inputs pre-rounded -> no cvt in the hot loop.
// Fragment loads LDS.128 over a shared k-permutation: thread (gid,tig) owns
// physical k {4tig..4tig+3}; addr mod 128B = 64*gid%128 + 16*tig => conflict-free.
// Hot loop per k-iter: 8 LDS.128 + 16 HMMA (tensor-bound).
// ---------------------------------------------------------------------------
#define GBM 128
#define GBN 64
#define GBK 16
#define NKT 16       // 256 / GBK

__global__ __launch_bounds__(256) void proj_gemm_tf32(
    const float* __restrict__ bq, const float* __restrict__ bk,
    const float* __restrict__ bv, const float* __restrict__ bs,
    int M)
{
    __shared__ float As[3][GBM][GBK];
    __shared__ float Bs[3][GBN][GBK];

    const float* W = g_wr[blockIdx.z];
    const float* bias;
    float* C;
    switch (blockIdx.z) {
        case 0:  bias = bq; C = g_q;    break;
        case 1:  bias = bk; C = g_k;    break;
        case 2:  bias = bv; C = g_v;    break;
        default: bias = bs; C = g_skip; break;
    }

    const int tid   = threadIdx.x;
    const int lane  = tid & 31;
    const int warp  = tid >> 5;
    const int warpM = warp & 3;
    const int warpN = warp >> 2;
    const int bm = blockIdx.y * GBM;
    const int bn = blockIdx.x * GBN;

    const int gid = lane >> 2;
    const int tig = lane & 3;

    const int ar0 = tid >> 2;
    const int akc = (tid & 3) * 4;
    const int br0 = tid >> 2;

    uint32_t sA = (uint32_t)__cvta_generic_to_shared(&As[0][0][0]);
    uint32_t sB = (uint32_t)__cvta_generic_to_shared(&Bs[0][0][0]);
    const uint32_t stageA = GBM * GBK * 4;
    const uint32_t stageB = GBN * GBK * 4;

    float acc[2][4][4] = {};

    auto load_stage = [&](int j, int st) {
        int kk = j * GBK;
        {
            int row = ar0;
            int grow = bm + row;
            cp16(sA + st * stageA + (row * GBK + akc) * 4,
                 g_featr + (size_t)grow * 256 + kk + akc, grow < M);
            row = ar0 + 64;
            grow = bm + row;
            cp16(sA + st * stageA + (row * GBK + akc) * 4,
                 g_featr + (size_t)grow * 256 + kk + akc, grow < M);
        }
        cp16(sB + st * stageB + (br0 * GBK + akc) * 4,
             W + (size_t)(bn + br0) * 256 + kk + akc, true);
        cp_commit();
    };

    load_stage(0, 0);
    load_stage(1, 1);

    for (int i = 0; i < NKT; i++) {
        if (i + 1 < NKT) cp_wait<1>(); else cp_wait<0>();
        __syncthreads();

        int st = i % 3;
        const uint4* As4 = (const uint4*)&As[st][0][0];   // [row*4 + tig]
        const uint4* Bs4 = (const uint4*)&Bs[st][0][0];

        uint4 a4[2][2];
        #pragma unroll
        for (int mt = 0; mt < 2; mt++) {
            int r = warpM * 32 + mt * 16 + gid;
            a4[mt][0] = As4[r * 4 + tig];
            a4[mt][1] = As4[(r + 8) * 4 + tig];
        }
        uint4 b4[4];
        #pragma unroll
        for (int nt = 0; nt < 4; nt++) {
            int nidx = warpN * 32 + nt * 8 + gid;
            b4[nt] = Bs4[nidx * 4 + tig];
        }

        // two 8-k mmas per tile pair: halves .xy and .zw (k-order invariant)
        #pragma unroll
        for (int mt = 0; mt < 2; mt++)
            #pragma unroll
            for (int nt = 0; nt < 4; nt++) {
                mma_tf32(acc[mt][nt],
                         a4[mt][0].x, a4[mt][1].x, a4[mt][0].y, a4[mt][1].y,
                         b4[nt].x, b4[nt].y);
                mma_tf32(acc[mt][nt],
                         a4[mt][0].z, a4[mt][1].z, a4[mt][0].w, a4[mt][1].w,
                         b4[nt].z, b4[nt].w);
            }

        if (i + 2 < NKT) load_stage(i + 2, (i + 2) % 3);
    }

    #pragma unroll
    for (int mt = 0; mt < 2; mt++) {
        int row = bm + warpM * 32 + mt * 16 + gid;
        #pragma unroll
        for (int nt = 0; nt < 4; nt++) {
            int col = bn + warpN * 32 + nt * 8 + tig * 2;
            float b0 = bias[col], b1 = bias[col + 1];
            if (row < M) {
                float2 o = make_float2(acc[mt][nt][0] + b0, acc[mt][nt][1] + b1);
                *(float2*)(C + (size_t)row * 256 + col) = o;
            }
            if (row + 8 < M) {
                float2 o = make_float2(acc[mt][nt][2] + b0, acc[mt][nt][3] + b1);
                *(float2*)(C + (size_t)(row + 8) * 256 + col) = o;
            }
        }
    }
}

// ---------------------------------------------------------------------------
// fused dst-centric attention + gated skip + LN + PReLU.  one warp per node.
// Scores are tiny (|e| < ~0.6): exp without max-subtraction is exact-equivalent.
// ---------------------------------------------------------------------------
__global__ __launch_bounds__(256) void fused_node(
    const float* __restrict__ Wg, const float* __restrict__ bg,
    const float* __restrict__ lnw, const float* __restrict__ lnb,
    const float* __restrict__ prelu_a, float* __restrict__ out, int N)
{
    int w    = (int)((blockIdx.x * 256u + threadIdx.x) >> 5);
    int lane = threadIdx.x & 31;
    if (w >= N) return;

    const float4* kr = (const float4*)(g_k + (size_t)w * HD);
    float4 k0 = kr[lane * 2], k1 = kr[lane * 2 + 1];

    float acc[8] = {};
    float den = 0.0f;

    int beg = g_rowptr[w];
    int end = g_rowptr[w + 1];
    for (int j = beg; j < end; j++) {
        int s = g_cidx[j];
        const float4* qr = (const float4*)(g_q + (size_t)s * HD);
        float4 q0 = qr[lane * 2], q1 = qr[lane * 2 + 1];
        const float4* vr = (const float4*)(g_v + (size_t)s * HD);
        float4 v0 = vr[lane * 2], v1 = vr[lane * 2 + 1];

        float p = q0.x * k0.x + q0.y * k0.y + q0.z * k0.z + q0.w * k0.w
                + q1.x * k1.x + q1.y * k1.y + q1.z * k1.z + q1.w * k1.w;
        p += __shfl_xor_sync(0xffffffffu, p, 4);
        p += __shfl_xor_sync(0xffffffffu, p, 2);
        p += __shfl_xor_sync(0xffffffffu, p, 1);
        float ex = __expf(p * 0.125f);
        den += ex;

        acc[0] += ex * v0.x; acc[1] += ex * v0.y;
        acc[2] += ex * v0.z; acc[3] += ex * v0.w;
        acc[4] += ex * v1.x; acc[5] += ex * v1.y;
        acc[6] += ex * v1.z; acc[7] += ex * v1.w;
    }

    float inv = (den > 0.0f) ? (1.0f / den) : 0.0f;
    float rs[8];
    #pragma unroll
    for (int i = 0; i < 8; i++) rs[i] = acc[i] * inv;

    const float4* skp = (const float4*)(g_skip + (size_t)w * HD);
    float4 s0 = skp[lane * 2], s1 = skp[lane * 2 + 1];
    float sk[8] = {s0.x, s0.y, s0.z, s0.w, s1.x, s1.y, s1.z, s1.w};

    float gp = 0.0f;
    #pragma unroll
    for (int i = 0; i < 8; i++) {
        int c = lane * 8 + i;
        gp += sk[i] * Wg[c] + rs[i] * Wg[256 + c] + (sk[i] - rs[i]) * Wg[512 + c];
    }
    #pragma unroll
    for (int m = 16; m >= 1; m >>= 1) gp += __shfl_xor_sync(0xffffffffu, gp, m);
    float g = 1.0f / (1.0f + expf(-(gp + bg[0])));

    float x[8];
    float sum = 0.0f;
    #pragma unroll
    for (int i = 0; i < 8; i++) {
        x[i] = g * sk[i] + (1.0f - g) * rs[i];
        sum += x[i];
    }
    #pragma unroll
    for (int m = 16; m >= 1; m >>= 1) sum += __shfl_xor_sync(0xffffffffu, sum, m);
    float mu = sum * (1.0f / 256.0f);

    float vs = 0.0f;
    #pragma unroll
    for (int i = 0; i < 8; i++) {
        float dd = x[i] - mu;
        vs += dd * dd;
    }
    #pragma unroll
    for (int m = 16; m >= 1; m >>= 1) vs += __shfl_xor_sync(0xffffffffu, vs, m);
    float rstd = rsqrtf(vs * (1.0f / 256.0f) + 1e-5f);

    float a = *prelu_a;
    float o[8];
    #pragma unroll
    for (int i = 0; i < 8; i++) {
        int c = lane * 8 + i;
        float y = (x[i] - mu) * rstd * lnw[c] + lnb[c];
        o[i] = (y >= 0.0f) ? y : a * y;
    }
    float4* op = (float4*)(out + (size_t)w * HD);
    op[lane * 2]     = make_float4(o[0], o[1], o[2], o[3]);
    op[lane * 2 + 1] = make_float4(o[4], o[5], o[6], o[7]);
}

// ---------------------------------------------------------------------------
extern "C" void kernel_launch(void* const* d_in, const int* in_sizes, int n_in,
                              void* d_out, int out_size)
{
    const float* feat = (const float*)d_in[0];
    const int*   src  = (const int*)d_in[1];
    const int*   dst  = (const int*)d_in[2];
    const float* Wq = (const float*)d_in[3];  const float* bq = (const float*)d_in[4];
    const float* Wk = (const float*)d_in[5];  const float* bk = (const float*)d_in[6];
    const float* Wv = (const float*)d_in[7];  const float* bv = (const float*)d_in[8];
    const float* Ws = (const float*)d_in[9];  const float* bs = (const float*)d_in[10];
    const float* Wg = (const float*)d_in[11]; const float* bg = (const float*)d_in[12];
    const float* lnw = (const float*)d_in[13];
    const float* lnb = (const float*)d_in[14];
    const float* pa  = (const float*)d_in[15];
    float* out = (float*)d_out;

    int M = in_sizes[0] / HD;   // 50000
    int E = in_sizes[1];        // 800000
    if (M > NN) M = NN;
    if (E > EE) E = EE;

    // CSR build
    zero_deg<<<(M + 255) / 256, 256>>>(M);
    hist_kernel<<<(E + 255) / 256, 256>>>(dst, E);
    scan_kernel<<<1, 1024>>>(M);
    scatter_kernel<<<(E + 255) / 256, 256>>>(src, dst, E);

    // pre-round inputs to tf32 bit patterns
    round_feat<<<(M * HD / 4 + 255) / 256, 256>>>(feat, M * HD / 4);
    round_w<<<(HD * HD / 4 + 255) / 256, 256>>>(Wq, Wk, Wv, Ws);

    // projections
    dim3 gg(HD / GBN, (M + GBM - 1) / GBM, 4);
    proj_gemm_tf32<<<gg, 256>>>(bq, bk, bv, bs, M);

    // fused attention + epilogue (one warp per node)
    fused_node<<<(M + 7) / 8, 256>>>(Wg, bg, lnw, lnb, pa, out, M);
}